// round 14
// baseline (speedup 1.0000x reference)
#include <cuda_runtime.h>
#include <cuda_fp16.h>
#include <math.h>
#include <stdint.h>

// Problem constants
#define BB    16384
#define HH    32
#define KVH   8
#define DD    128
#define RBIT  128
#define HID   4096      // H*D
#define KOUT  1024      // KVH*D
#define KA    4096      // GEMM K (plain fp16)
#define MCH   8192      // M-chunk (BB/2)

// ---------------------------------------------------------------------------
// Device scratch (no allocations allowed)
// ---------------------------------------------------------------------------
__device__ __half g_Aq[(size_t)BB * KA];        // 128 MB
__device__ __half g_Ak[(size_t)BB * KA];        // 128 MB
__device__ __half g_Wq[(size_t)HID * KA];       // 32 MB  [N,K]
__device__ __half g_Wk[(size_t)KOUT * KA];      // 8 MB   [N,K]
__device__ float g_Q[(size_t)BB * HID];         // 256 MB
__device__ float g_K[(size_t)BB * KOUT];        // 64 MB
__device__ __half g_hwT[RBIT * DD];             // 32 KB

// ---------------------------------------------------------------------------
// Helpers
// ---------------------------------------------------------------------------
__device__ __forceinline__ uint32_t smem_u32(const void* p) {
    uint32_t a;
    asm("{ .reg .u64 t; cvta.to.shared.u64 t, %1; cvt.u32.u64 %0, t; }"
        : "=r"(a) : "l"(p));
    return a;
}
__device__ __forceinline__ uint32_t sw128(uint32_t off) {
    return off ^ ((off >> 3) & 0x70);   // Swizzle<3,4,3>
}
__device__ __forceinline__ float tanh_fast(float x) {
    float r;
    asm("tanh.approx.f32 %0, %1;" : "=f"(r) : "f"(x));
    return r;
}

#define CP16(dst, src) \
    asm volatile("cp.async.cg.shared.global [%0], [%1], 16;" \
                 :: "r"(dst), "l"(src) : "memory")
#define CP_COMMIT() asm volatile("cp.async.commit_group;" ::: "memory")
#define CP_WAIT(n)  asm volatile("cp.async.wait_group %0;" :: "n"(n) : "memory")

#define LDSM4(r, addr) \
    asm volatile("ldmatrix.sync.aligned.m8n8.x4.shared.b16 {%0,%1,%2,%3}, [%4];" \
                 : "=r"((r)[0]), "=r"((r)[1]), "=r"((r)[2]), "=r"((r)[3]) \
                 : "r"(addr))

__device__ __forceinline__ void mma16816(float* d, const uint32_t* a,
                                         const uint32_t* b) {
    asm volatile(
        "mma.sync.aligned.m16n8k16.row.col.f32.f16.f16.f32 "
        "{%0,%1,%2,%3}, {%4,%5,%6,%7}, {%8,%9}, {%0,%1,%2,%3};"
        : "+f"(d[0]), "+f"(d[1]), "+f"(d[2]), "+f"(d[3])
        : "r"(a[0]), "r"(a[1]), "r"(a[2]), "r"(a[3]), "r"(b[0]), "r"(b[1]));
}

__device__ __forceinline__ uint32_t pack_h2(__half a, __half b) {
    __half2 t = __halves2half2(a, b);
    return *reinterpret_cast<uint32_t*>(&t);
}

// ---------------------------------------------------------------------------
// Conversion: fp32 [rows, 4096] -> fp16 [rows, 4096]
// ---------------------------------------------------------------------------
__global__ __launch_bounds__(256) void tofp16_kernel(
    const float4* __restrict__ X, uint2* __restrict__ Y, size_t n4)
{
    size_t i = (size_t)blockIdx.x * 256 + threadIdx.x;
    if (i >= n4) return;
    float4 v = X[i];
    Y[i] = make_uint2(pack_h2(__float2half(v.x), __float2half(v.y)),
                      pack_h2(__float2half(v.z), __float2half(v.w)));
}

// ---------------------------------------------------------------------------
// Conversion + transpose: W fp32 [4096, N] -> Wt fp16 [N, 4096]
// ---------------------------------------------------------------------------
__global__ __launch_bounds__(256) void split_w_kernel(
    const float* __restrict__ W, __half* __restrict__ Wt, int N)
{
    __shared__ float t[32][33];
    int n0 = blockIdx.x * 32, k0 = blockIdx.y * 32;
    int tx = threadIdx.x & 31, ty = threadIdx.x >> 5;
    #pragma unroll
    for (int i = 0; i < 4; i++)
        t[ty + i * 8][tx] = W[(size_t)(k0 + ty + i * 8) * N + n0 + tx];
    __syncthreads();
    #pragma unroll
    for (int i = 0; i < 4; i++) {
        int n = n0 + ty + i * 8;
        int k = k0 + tx;
        Wt[(size_t)n * KA + k] = __float2half(t[tx][ty + i * 8]);
    }
}

// ---------------------------------------------------------------------------
// hash_w fp32 [d=128][r=128] -> hwT fp16 [r][d]
// ---------------------------------------------------------------------------
__global__ __launch_bounds__(256) void hw16_kernel(
    const float* __restrict__ hw, __half* __restrict__ hwT)
{
    int t = blockIdx.x * 256 + threadIdx.x;     // 16384 total
    int d = t >> 7, r = t & 127;
    hwT[r * DD + d] = __float2half(hw[d * RBIT + r]);
}

// ---------------------------------------------------------------------------
// HMMA GEMM: C[M,N] = A[M,K] @ W[N,K]^T + bias (plain fp16, K=4096)
// BM=BN=128, BK=64, 3-stage cp.async, 256 threads, 2 CTAs/SM. Frozen.
// ---------------------------------------------------------------------------
#define BM 128
#define BN 128
#define BKK 64
#define STAGES 3
#define ASTG (BM * BKK * 2)                // 16384 bytes per stage
#define GEMM_SMEM (2 * STAGES * ASTG)      // 98304
#define NIT (KA / BKK)                     // 64

__global__ __launch_bounds__(256, 2) void gemm_mma_kernel(
    const __half* __restrict__ A, const __half* __restrict__ W,
    const float* __restrict__ bias, float* __restrict__ C, int N)
{
    extern __shared__ char smem[];
    const uint32_t sA = smem_u32(smem);
    const uint32_t sB = sA + STAGES * ASTG;

    const int tid  = threadIdx.x;
    const int lane = tid & 31;
    const int wid  = tid >> 5;
    const int bm = blockIdx.y * BM;
    const int bn = blockIdx.x * BN;
    const int wm = (wid & 1) * 64;
    const int wn = (wid >> 1) * 32;

    const int lr = tid >> 3;
    const int lc = tid & 7;
    const __half* Ab = A + (size_t)(bm + lr) * KA + lc * 8;
    const __half* Wb = W + (size_t)(bn + lr) * KA + lc * 8;
    const uint32_t sdst = sw128(lr * 128 + lc * 16);

    float acc[4][4][4];
    #pragma unroll
    for (int mt = 0; mt < 4; mt++)
        #pragma unroll
        for (int nt = 0; nt < 4; nt++)
            #pragma unroll
            for (int e = 0; e < 4; e++) acc[mt][nt][e] = 0.f;

    const int bi = lane >> 3;
    const int rr = lane & 7;
    const uint32_t a_row = wm + (bi & 1) * 8 + rr;
    const uint32_t a_col = (bi >> 1) * 16;
    const uint32_t b_row = wn + (bi >> 1) * 8 + rr;
    const uint32_t b_col = (bi & 1) * 16;

    auto load_tile = [&](int stg, int tile) {
        const int k0 = tile * BKK;
        const uint32_t da = sA + stg * ASTG + sdst;
        const uint32_t db = sB + stg * ASTG + sdst;
        #pragma unroll
        for (int i = 0; i < 4; i++) {
            CP16(da + i * 32 * 128, Ab + (size_t)i * 32 * KA + k0);
            CP16(db + i * 32 * 128, Wb + (size_t)i * 32 * KA + k0);
        }
    };

    #pragma unroll
    for (int s = 0; s < STAGES - 1; s++) {
        load_tile(s, s);
        CP_COMMIT();
    }

    int stg = 0;
    #pragma unroll 1
    for (int i = 0; i < NIT; i++) {
        CP_WAIT(STAGES - 2);
        __syncthreads();

        const int nxt = i + STAGES - 1;
        int nstg = stg + STAGES - 1;
        if (nstg >= STAGES) nstg -= STAGES;
        if (nxt < NIT) load_tile(nstg, nxt);
        CP_COMMIT();

        const uint32_t abase = sA + stg * ASTG;
        const uint32_t bbase = sB + stg * ASTG;

        #pragma unroll
        for (int kp = 0; kp < 4; kp++) {
            uint32_t afr[4][4];
            #pragma unroll
            for (int mt = 0; mt < 4; mt++) {
                uint32_t ad = abase +
                    sw128((a_row + mt * 16) * 128 + kp * 32 + a_col);
                LDSM4(afr[mt], ad);
            }
            uint32_t bfr[4][2];
            #pragma unroll
            for (int p = 0; p < 2; p++) {
                uint32_t r4[4];
                uint32_t bd = bbase +
                    sw128((b_row + p * 16) * 128 + kp * 32 + b_col);
                LDSM4(r4, bd);
                bfr[p * 2][0]     = r4[0];
                bfr[p * 2][1]     = r4[1];
                bfr[p * 2 + 1][0] = r4[2];
                bfr[p * 2 + 1][1] = r4[3];
            }
            #pragma unroll
            for (int mt = 0; mt < 4; mt++)
                #pragma unroll
                for (int nt = 0; nt < 4; nt++)
                    mma16816(acc[mt][nt], afr[mt], bfr[nt]);
        }
        if (++stg == STAGES) stg = 0;
    }

    const int gr  = lane >> 2;
    const int gc2 = (lane & 3) * 2;
    #pragma unroll
    for (int mt = 0; mt < 4; mt++) {
        const int r0 = bm + wm + mt * 16 + gr;
        #pragma unroll
        for (int nt = 0; nt < 4; nt++) {
            const int col = bn + wn + nt * 8 + gc2;
            const float2 bv = *reinterpret_cast<const float2*>(&bias[col]);
            float2 o0 = make_float2(acc[mt][nt][0] + bv.x, acc[mt][nt][1] + bv.y);
            float2 o1 = make_float2(acc[mt][nt][2] + bv.x, acc[mt][nt][3] + bv.y);
            *reinterpret_cast<float2*>(&C[(size_t)r0 * N + col]) = o0;
            *reinterpret_cast<float2*>(&C[(size_t)(r0 + 8) * N + col]) = o1;
        }
    }
}

// ---------------------------------------------------------------------------
// HMMA tail: one block per (16 b-rows, kvh). 5 warps, fp16 codes, 3 CTAs/SM.
// b_base selects the M-chunk.
// ---------------------------------------------------------------------------
#define T_A_OFF    0
#define T_A_PLANE  10240
#define T_HW_OFF   20480
#define T_HW_PLANE 16384
#define T_CODE_OFF 53248                    // [80][132] fp16
#define T_CODE_STR 132
#define T_SN_OFF   (T_CODE_OFF + 80 * T_CODE_STR * 2)
#define TAIL_SMEM  (T_SN_OFF + 320 + 64)

__global__ __launch_bounds__(160, 3) void tail_mma_kernel(
    const float* __restrict__ Q, const float* __restrict__ Kp,
    const __half* __restrict__ hwT, float* __restrict__ out, int b_base)
{
    extern __shared__ char ts[];
    const uint32_t sbase = smem_u32(ts);
    __half* codes = reinterpret_cast<__half*>(ts + T_CODE_OFF);
    float* snorm  = reinterpret_cast<float*>(ts + T_SN_OFF);

    const int tid  = threadIdx.x;
    const int lane = tid & 31;
    const int wid  = tid >> 5;
    const int b0   = b_base + (blockIdx.x >> 3) * 16;
    const int kvh  = blockIdx.x & 7;
    const float inv = 0.08838834764831845f;

    for (int c = tid; c < 2048; c += 160) {
        int row = c >> 4, seg = c & 15;
        int pl = seg >> 3;
        uint4 v = *reinterpret_cast<const uint4*>(
            hwT + (size_t)row * DD + pl * 64 + (seg & 7) * 8);
        uint32_t off = T_HW_OFF + pl * T_HW_PLANE +
                       sw128(row * 128 + (seg & 7) * 16);
        *reinterpret_cast<uint4*>(ts + off) = v;
    }

    {
        const int i = lane >> 1;
        const int h = lane & 1;
        const int b = b0 + i;
        const float* kptr = Kp + (size_t)b * KOUT + kvh * DD + h * 64;
        if (wid < 4) {
            const int head = kvh * 4 + wid;
            const float* qptr = Q + (size_t)b * HID + head * DD + h * 64;
            const int arow = wid * 16 + i;
            float dot = 0.f, qn2 = 0.f;
            #pragma unroll
            for (int c = 0; c < 8; c++) {
                float4 qa = __ldg(reinterpret_cast<const float4*>(qptr + c * 8));
                float4 qb = __ldg(reinterpret_cast<const float4*>(qptr + c * 8 + 4));
                float4 ka = __ldg(reinterpret_cast<const float4*>(kptr + c * 8));
                float4 kb = __ldg(reinterpret_cast<const float4*>(kptr + c * 8 + 4));
                dot += qa.x * ka.x + qa.y * ka.y + qa.z * ka.z + qa.w * ka.w +
                       qb.x * kb.x + qb.y * kb.y + qb.z * kb.z + qb.w * kb.w;
                qn2 += qa.x * qa.x + qa.y * qa.y + qa.z * qa.z + qa.w * qa.w +
                       qb.x * qb.x + qb.y * qb.y + qb.z * qb.z + qb.w * qb.w;
                uint4 u = make_uint4(
                    pack_h2(__float2half(qa.x), __float2half(qa.y)),
                    pack_h2(__float2half(qa.z), __float2half(qa.w)),
                    pack_h2(__float2half(qb.x), __float2half(qb.y)),
                    pack_h2(__float2half(qb.z), __float2half(qb.w)));
                uint32_t off = T_A_OFF + h * T_A_PLANE +
                               sw128(arow * 128 + c * 16);
                *reinterpret_cast<uint4*>(ts + off) = u;
            }
            dot += __shfl_xor_sync(0xffffffffu, dot, 1);
            qn2 += __shfl_xor_sync(0xffffffffu, qn2, 1);
            if (h == 0) {
                out[(size_t)b * HH + head] = dot * inv;
                snorm[arow] = qn2;
            }
        } else {
            const int arow = 64 + i;
            float kn2 = 0.f;
            #pragma unroll
            for (int c = 0; c < 8; c++) {
                float4 ka = __ldg(reinterpret_cast<const float4*>(kptr + c * 8));
                float4 kb = __ldg(reinterpret_cast<const float4*>(kptr + c * 8 + 4));
                kn2 += ka.x * ka.x + ka.y * ka.y + ka.z * ka.z + ka.w * ka.w +
                       kb.x * kb.x + kb.y * kb.y + kb.z * kb.z + kb.w * kb.w;
                uint4 u = make_uint4(
                    pack_h2(__float2half(ka.x), __float2half(ka.y)),
                    pack_h2(__float2half(ka.z), __float2half(ka.w)),
                    pack_h2(__float2half(kb.x), __float2half(kb.y)),
                    pack_h2(__float2half(kb.z), __float2half(kb.w)));
                uint32_t off = T_A_OFF + h * T_A_PLANE +
                               sw128(arow * 128 + c * 16);
                *reinterpret_cast<uint4*>(ts + off) = u;
            }
            kn2 += __shfl_xor_sync(0xffffffffu, kn2, 1);
            if (h == 0) snorm[arow] = kn2;
        }
    }
    __syncthreads();

    {
        const int bi = lane >> 3;
        const int rr = lane & 7;
        const uint32_t a_row = wid * 16 + (bi & 1) * 8 + rr;
        const uint32_t a_col = (bi >> 1) * 16;
        const uint32_t b_rowb = (bi >> 1) * 8 + rr;
        const uint32_t b_col = (bi & 1) * 16;

        float acc[16][4];
        #pragma unroll
        for (int n = 0; n < 16; n++)
            #pragma unroll
            for (int e = 0; e < 4; e++) acc[n][e] = 0.f;

        #pragma unroll
        for (int kp = 0; kp < 8; kp++) {
            const int pl = kp >> 2;
            const int kb = (kp & 3) * 32;
            uint32_t afr[4];
            LDSM4(afr, sbase + T_A_OFF + pl * T_A_PLANE +
                       sw128(a_row * 128 + kb + a_col));
            #pragma unroll
            for (int nt = 0; nt < 8; nt++) {
                uint32_t r4[4];
                LDSM4(r4, sbase + T_HW_OFF + pl * T_HW_PLANE +
                          sw128((nt * 16 + b_rowb) * 128 + kb + b_col));
                uint32_t bf0[2] = {r4[0], r4[1]};
                uint32_t bf1[2] = {r4[2], r4[3]};
                mma16816(acc[nt * 2], afr, bf0);
                mma16816(acc[nt * 2 + 1], afr, bf1);
            }
        }

        const int gr  = lane >> 2;
        const int gc2 = (lane & 3) * 2;
        #pragma unroll
        for (int n = 0; n < 16; n++) {
            const int col = n * 8 + gc2;
            const int row0 = wid * 16 + gr;
            __half2 lo = __halves2half2(
                __float2half(0.5f * (tanh_fast(acc[n][0]) + 1.0f)),
                __float2half(0.5f * (tanh_fast(acc[n][1]) + 1.0f)));
            __half2 hi = __halves2half2(
                __float2half(0.5f * (tanh_fast(acc[n][2]) + 1.0f)),
                __float2half(0.5f * (tanh_fast(acc[n][3]) + 1.0f)));
            *reinterpret_cast<__half2*>(&codes[row0 * T_CODE_STR + col]) = lo;
            *reinterpret_cast<__half2*>(&codes[(row0 + 8) * T_CODE_STR + col]) = hi;
        }
    }
    __syncthreads();

    if (tid < 128) {
        const int qrow = tid >> 1;
        const int h = tid & 1;
        const int krow = 64 + (qrow & 15);
        const __half* qc = &codes[qrow * T_CODE_STR + h * 64];
        const __half* kc = &codes[krow * T_CODE_STR + h * 64];
        float s = 0.f;
        #pragma unroll
        for (int j = 0; j < 16; j++) {
            uint2 qv = *reinterpret_cast<const uint2*>(qc + j * 4);
            uint2 kv = *reinterpret_cast<const uint2*>(kc + j * 4);
            __half2 q0 = *reinterpret_cast<__half2*>(&qv.x);
            __half2 q1 = *reinterpret_cast<__half2*>(&qv.y);
            __half2 k0 = *reinterpret_cast<__half2*>(&kv.x);
            __half2 k1 = *reinterpret_cast<__half2*>(&kv.y);
            float2 a0 = __half22float2(q0), b0f = __half22float2(k0);
            float2 a1 = __half22float2(q1), b1f = __half22float2(k1);
            s += fabsf(a0.x - b0f.x) + fabsf(a0.y - b0f.y) +
                 fabsf(a1.x - b1f.x) + fabsf(a1.y - b1f.y);
        }
        s += __shfl_xor_sync(0xffffffffu, s, 1);
        if (h == 0) {
            const int i = qrow & 15;
            const int g = qrow >> 4;
            const int b = b0 + i;
            const float qn = sqrtf(snorm[qrow]);
            const float kn = sqrtf(snorm[64 + i]);
            out[(size_t)BB * HH + (size_t)b * HH + kvh * 4 + g] =
                (1.0f - 2.0f * s / (float)RBIT) * qn * kn * inv;
        }
    }
}

// ---------------------------------------------------------------------------
// Stream/event resources: created once on first (uncaptured) call.
// ---------------------------------------------------------------------------
struct SideStream {
    cudaStream_t sA, sB, sW;
    cudaEvent_t evFork, evWq, evWk;
    cudaEvent_t evQ[2], evK[2], evC[2], evT;
    SideStream() {
        cudaStreamCreateWithFlags(&sA, cudaStreamNonBlocking);
        cudaStreamCreateWithFlags(&sB, cudaStreamNonBlocking);
        cudaStreamCreateWithFlags(&sW, cudaStreamNonBlocking);
        cudaEventCreateWithFlags(&evFork, cudaEventDisableTiming);
        cudaEventCreateWithFlags(&evWq, cudaEventDisableTiming);
        cudaEventCreateWithFlags(&evWk, cudaEventDisableTiming);
        for (int c = 0; c < 2; c++) {
            cudaEventCreateWithFlags(&evQ[c], cudaEventDisableTiming);
            cudaEventCreateWithFlags(&evK[c], cudaEventDisableTiming);
            cudaEventCreateWithFlags(&evC[c], cudaEventDisableTiming);
        }
        cudaEventCreateWithFlags(&evT, cudaEventDisableTiming);
    }
};
static SideStream& side() { static SideStream s; return s; }

// ---------------------------------------------------------------------------
extern "C" void kernel_launch(void* const* d_in, const int* in_sizes, int n_in,
                              void* d_out, int out_size)
{
    const float* q_hidden = (const float*)d_in[0];
    const float* k_hidden = (const float*)d_in[1];
    const float* q_w      = (const float*)d_in[2];
    const float* q_b      = (const float*)d_in[3];
    const float* k_w      = (const float*)d_in[4];
    const float* k_b      = (const float*)d_in[5];
    const float* hash_w   = (const float*)d_in[6];
    float* out = (float*)d_out;

    void *aq, *ak, *wq, *wk, *qp, *kp, *hwp;
    cudaGetSymbolAddress(&aq, g_Aq);
    cudaGetSymbolAddress(&ak, g_Ak);
    cudaGetSymbolAddress(&wq, g_Wq);
    cudaGetSymbolAddress(&wk, g_Wk);
    cudaGetSymbolAddress(&qp, g_Q);
    cudaGetSymbolAddress(&kp, g_K);
    cudaGetSymbolAddress(&hwp, g_hwT);

    cudaFuncSetAttribute(gemm_mma_kernel,
                         cudaFuncAttributeMaxDynamicSharedMemorySize, GEMM_SMEM);
    cudaFuncSetAttribute(tail_mma_kernel,
                         cudaFuncAttributeMaxDynamicSharedMemorySize, TAIL_SMEM);

    SideStream& ss = side();
    const size_t c4q = (size_t)MCH * HID / 4;   // float4/uint2 elems per Q chunk
    const size_t c4k = (size_t)MCH * HID / 4;   // same hidden width for K input

    cudaEventRecord(ss.evFork, 0);

    // ---- sW: weight transposes ----
    cudaStreamWaitEvent(ss.sW, ss.evFork, 0);
    split_w_kernel<<<dim3(HID / 32, HID / 32), 256, 0, ss.sW>>>(
        q_w, (__half*)wq, HID);
    cudaEventRecord(ss.evWq, ss.sW);
    split_w_kernel<<<dim3(KOUT / 32, HID / 32), 256, 0, ss.sW>>>(
        k_w, (__half*)wk, KOUT);
    cudaEventRecord(ss.evWk, ss.sW);

    // ---- sA: Q-activation conversion chunks ----
    cudaStreamWaitEvent(ss.sA, ss.evFork, 0);
    for (int c = 0; c < 2; c++) {
        tofp16_kernel<<<(unsigned)(c4q / 256), 256, 0, ss.sA>>>(
            (const float4*)q_hidden + c * c4q,
            (uint2*)aq + c * c4q, c4q);
        cudaEventRecord(ss.evQ[c], ss.sA);
    }

    // ---- sB: hash prep + K-activation conversion chunks ----
    cudaStreamWaitEvent(ss.sB, ss.evFork, 0);
    hw16_kernel<<<64, 256, 0, ss.sB>>>(hash_w, (__half*)hwp);
    for (int c = 0; c < 2; c++) {
        tofp16_kernel<<<(unsigned)(c4k / 256), 256, 0, ss.sB>>>(
            (const float4*)k_hidden + c * c4k,
            (uint2*)ak + c * c4k, c4k);
        cudaEventRecord(ss.evK[c], ss.sB);
    }

    // ---- stream 0: chunked GEMMs ----
    for (int c = 0; c < 2; c++) {
        cudaStreamWaitEvent(0, ss.evQ[c], 0);
        if (c == 0) cudaStreamWaitEvent(0, ss.evWq, 0);
        gemm_mma_kernel<<<dim3(HID / BN, MCH / BM), 256, GEMM_SMEM>>>(
            (const __half*)aq + (size_t)c * MCH * KA, (const __half*)wq,
            q_b, (float*)qp + (size_t)c * MCH * HID, HID);
        cudaStreamWaitEvent(0, ss.evK[c], 0);
        if (c == 0) cudaStreamWaitEvent(0, ss.evWk, 0);
        gemm_mma_kernel<<<dim3(KOUT / BN, MCH / BM), 256, GEMM_SMEM>>>(
            (const __half*)ak + (size_t)c * MCH * KA, (const __half*)wk,
            k_b, (float*)kp + (size_t)c * MCH * KOUT, KOUT);
        cudaEventRecord(ss.evC[c], 0);
    }

    // ---- sB: chunked tails (tail0 overlaps chunk-1 GEMMs) ----
    for (int c = 0; c < 2; c++) {
        cudaStreamWaitEvent(ss.sB, ss.evC[c], 0);
        tail_mma_kernel<<<(MCH / 16) * KVH, 160, TAIL_SMEM, ss.sB>>>(
            (const float*)qp, (const float*)kp, (const __half*)hwp, out,
            c * MCH);
    }
    cudaEventRecord(ss.evT, ss.sB);
    cudaStreamWaitEvent(0, ss.evT, 0);
}

// round 15
// speedup vs baseline: 1.1043x; 1.1043x over previous
#include <cuda_runtime.h>
#include <cuda_fp16.h>
#include <math.h>
#include <stdint.h>

// Problem constants
#define BB    16384
#define HH    32
#define KVH   8
#define DD    128
#define RBIT  128
#define HID   4096      // H*D
#define KOUT  1024      // KVH*D
#define KA    4096      // GEMM K (plain fp16)

// ---------------------------------------------------------------------------
// Device scratch (no allocations allowed)
// ---------------------------------------------------------------------------
__device__ __half g_Aq[(size_t)BB * KA];        // 128 MB
__device__ __half g_Ak[(size_t)BB * KA];        // 128 MB
__device__ __half g_Wq[(size_t)HID * KA];       // 32 MB  [N,K]
__device__ __half g_Wk[(size_t)KOUT * KA];      // 8 MB   [N,K]
__device__ __half g_Q[(size_t)BB * HID];        // 128 MB (fp16 states)
__device__ __half g_K[(size_t)BB * KOUT];       // 32 MB  (fp16 states)
__device__ __half g_hwT[RBIT * DD];             // 32 KB

// ---------------------------------------------------------------------------
// Helpers
// ---------------------------------------------------------------------------
__device__ __forceinline__ uint32_t smem_u32(const void* p) {
    uint32_t a;
    asm("{ .reg .u64 t; cvta.to.shared.u64 t, %1; cvt.u32.u64 %0, t; }"
        : "=r"(a) : "l"(p));
    return a;
}
__device__ __forceinline__ uint32_t sw128(uint32_t off) {
    return off ^ ((off >> 3) & 0x70);   // Swizzle<3,4,3>
}
__device__ __forceinline__ float tanh_fast(float x) {
    float r;
    asm("tanh.approx.f32 %0, %1;" : "=f"(r) : "f"(x));
    return r;
}

#define CP16(dst, src) \
    asm volatile("cp.async.cg.shared.global [%0], [%1], 16;" \
                 :: "r"(dst), "l"(src) : "memory")
#define CP_COMMIT() asm volatile("cp.async.commit_group;" ::: "memory")
#define CP_WAIT(n)  asm volatile("cp.async.wait_group %0;" :: "n"(n) : "memory")

#define LDSM4(r, addr) \
    asm volatile("ldmatrix.sync.aligned.m8n8.x4.shared.b16 {%0,%1,%2,%3}, [%4];" \
                 : "=r"((r)[0]), "=r"((r)[1]), "=r"((r)[2]), "=r"((r)[3]) \
                 : "r"(addr))

__device__ __forceinline__ void mma16816(float* d, const uint32_t* a,
                                         const uint32_t* b) {
    asm volatile(
        "mma.sync.aligned.m16n8k16.row.col.f32.f16.f16.f32 "
        "{%0,%1,%2,%3}, {%4,%5,%6,%7}, {%8,%9}, {%0,%1,%2,%3};"
        : "+f"(d[0]), "+f"(d[1]), "+f"(d[2]), "+f"(d[3])
        : "r"(a[0]), "r"(a[1]), "r"(a[2]), "r"(a[3]), "r"(b[0]), "r"(b[1]));
}

__device__ __forceinline__ uint32_t pack_h2(__half a, __half b) {
    __half2 t = __halves2half2(a, b);
    return *reinterpret_cast<uint32_t*>(&t);
}

// ---------------------------------------------------------------------------
// Conversion: fp32 [rows, 4096] -> fp16 [rows, 4096]
// ---------------------------------------------------------------------------
__global__ __launch_bounds__(256) void tofp16_kernel(
    const float4* __restrict__ X, uint2* __restrict__ Y, size_t n4)
{
    size_t i = (size_t)blockIdx.x * 256 + threadIdx.x;
    if (i >= n4) return;
    float4 v = X[i];
    Y[i] = make_uint2(pack_h2(__float2half(v.x), __float2half(v.y)),
                      pack_h2(__float2half(v.z), __float2half(v.w)));
}

// ---------------------------------------------------------------------------
// Conversion + transpose: W fp32 [4096, N] -> Wt fp16 [N, 4096]
// ---------------------------------------------------------------------------
__global__ __launch_bounds__(256) void split_w_kernel(
    const float* __restrict__ W, __half* __restrict__ Wt, int N)
{
    __shared__ float t[32][33];
    int n0 = blockIdx.x * 32, k0 = blockIdx.y * 32;
    int tx = threadIdx.x & 31, ty = threadIdx.x >> 5;
    #pragma unroll
    for (int i = 0; i < 4; i++)
        t[ty + i * 8][tx] = W[(size_t)(k0 + ty + i * 8) * N + n0 + tx];
    __syncthreads();
    #pragma unroll
    for (int i = 0; i < 4; i++) {
        int n = n0 + ty + i * 8;
        int k = k0 + tx;
        Wt[(size_t)n * KA + k] = __float2half(t[tx][ty + i * 8]);
    }
}

// ---------------------------------------------------------------------------
// hash_w fp32 [d=128][r=128] -> hwT fp16 [r][d]
// ---------------------------------------------------------------------------
__global__ __launch_bounds__(256) void hw16_kernel(
    const float* __restrict__ hw, __half* __restrict__ hwT)
{
    int t = blockIdx.x * 256 + threadIdx.x;     // 16384 total
    int d = t >> 7, r = t & 127;
    hwT[r * DD + d] = __float2half(hw[d * RBIT + r]);
}

// ---------------------------------------------------------------------------
// HMMA GEMM: C[M,N] = A[M,K] @ W[N,K]^T + bias, fp16 output.
// BM=BN=128, BK=64, 3-stage cp.async, 256 threads, 2 CTAs/SM. Mainloop frozen.
// ---------------------------------------------------------------------------
#define BM 128
#define BN 128
#define BKK 64
#define STAGES 3
#define ASTG (BM * BKK * 2)                // 16384 bytes per stage
#define GEMM_SMEM (2 * STAGES * ASTG)      // 98304
#define NIT (KA / BKK)                     // 64

__global__ __launch_bounds__(256, 2) void gemm_mma_kernel(
    const __half* __restrict__ A, const __half* __restrict__ W,
    const float* __restrict__ bias, __half* __restrict__ C, int N)
{
    extern __shared__ char smem[];
    const uint32_t sA = smem_u32(smem);
    const uint32_t sB = sA + STAGES * ASTG;

    const int tid  = threadIdx.x;
    const int lane = tid & 31;
    const int wid  = tid >> 5;
    const int bm = blockIdx.y * BM;
    const int bn = blockIdx.x * BN;
    const int wm = (wid & 1) * 64;
    const int wn = (wid >> 1) * 32;

    const int lr = tid >> 3;
    const int lc = tid & 7;
    const __half* Ab = A + (size_t)(bm + lr) * KA + lc * 8;
    const __half* Wb = W + (size_t)(bn + lr) * KA + lc * 8;
    const uint32_t sdst = sw128(lr * 128 + lc * 16);

    float acc[4][4][4];
    #pragma unroll
    for (int mt = 0; mt < 4; mt++)
        #pragma unroll
        for (int nt = 0; nt < 4; nt++)
            #pragma unroll
            for (int e = 0; e < 4; e++) acc[mt][nt][e] = 0.f;

    const int bi = lane >> 3;
    const int rr = lane & 7;
    const uint32_t a_row = wm + (bi & 1) * 8 + rr;
    const uint32_t a_col = (bi >> 1) * 16;
    const uint32_t b_row = wn + (bi >> 1) * 8 + rr;
    const uint32_t b_col = (bi & 1) * 16;

    auto load_tile = [&](int stg, int tile) {
        const int k0 = tile * BKK;
        const uint32_t da = sA + stg * ASTG + sdst;
        const uint32_t db = sB + stg * ASTG + sdst;
        #pragma unroll
        for (int i = 0; i < 4; i++) {
            CP16(da + i * 32 * 128, Ab + (size_t)i * 32 * KA + k0);
            CP16(db + i * 32 * 128, Wb + (size_t)i * 32 * KA + k0);
        }
    };

    #pragma unroll
    for (int s = 0; s < STAGES - 1; s++) {
        load_tile(s, s);
        CP_COMMIT();
    }

    int stg = 0;
    #pragma unroll 1
    for (int i = 0; i < NIT; i++) {
        CP_WAIT(STAGES - 2);
        __syncthreads();

        const int nxt = i + STAGES - 1;
        int nstg = stg + STAGES - 1;
        if (nstg >= STAGES) nstg -= STAGES;
        if (nxt < NIT) load_tile(nstg, nxt);
        CP_COMMIT();

        const uint32_t abase = sA + stg * ASTG;
        const uint32_t bbase = sB + stg * ASTG;

        #pragma unroll
        for (int kp = 0; kp < 4; kp++) {
            uint32_t afr[4][4];
            #pragma unroll
            for (int mt = 0; mt < 4; mt++) {
                uint32_t ad = abase +
                    sw128((a_row + mt * 16) * 128 + kp * 32 + a_col);
                LDSM4(afr[mt], ad);
            }
            uint32_t bfr[4][2];
            #pragma unroll
            for (int p = 0; p < 2; p++) {
                uint32_t r4[4];
                uint32_t bd = bbase +
                    sw128((b_row + p * 16) * 128 + kp * 32 + b_col);
                LDSM4(r4, bd);
                bfr[p * 2][0]     = r4[0];
                bfr[p * 2][1]     = r4[1];
                bfr[p * 2 + 1][0] = r4[2];
                bfr[p * 2 + 1][1] = r4[3];
            }
            #pragma unroll
            for (int mt = 0; mt < 4; mt++)
                #pragma unroll
                for (int nt = 0; nt < 4; nt++)
                    mma16816(acc[mt][nt], afr[mt], bfr[nt]);
        }
        if (++stg == STAGES) stg = 0;
    }

    // Epilogue: + bias (fp32), store fp16
    const int gr  = lane >> 2;
    const int gc2 = (lane & 3) * 2;
    #pragma unroll
    for (int mt = 0; mt < 4; mt++) {
        const int r0 = bm + wm + mt * 16 + gr;
        #pragma unroll
        for (int nt = 0; nt < 4; nt++) {
            const int col = bn + wn + nt * 8 + gc2;
            const float2 bv = *reinterpret_cast<const float2*>(&bias[col]);
            __half2 o0 = __floats2half2_rn(acc[mt][nt][0] + bv.x,
                                           acc[mt][nt][1] + bv.y);
            __half2 o1 = __floats2half2_rn(acc[mt][nt][2] + bv.x,
                                           acc[mt][nt][3] + bv.y);
            *reinterpret_cast<__half2*>(&C[(size_t)r0 * N + col]) = o0;
            *reinterpret_cast<__half2*>(&C[(size_t)(r0 + 8) * N + col]) = o1;
        }
    }
}

// ---------------------------------------------------------------------------
// HMMA tail: one block per (16 b-rows, kvh). 5 warps, fp16 Q/K in, fp16 codes,
// 3 CTAs/SM. Staging is a raw fp16 copy; dot/norms accumulate in fp32.
// ---------------------------------------------------------------------------
#define T_A_OFF    0
#define T_A_PLANE  10240
#define T_HW_OFF   20480
#define T_HW_PLANE 16384
#define T_CODE_OFF 53248                    // [80][132] fp16
#define T_CODE_STR 132
#define T_SN_OFF   (T_CODE_OFF + 80 * T_CODE_STR * 2)
#define TAIL_SMEM  (T_SN_OFF + 320 + 64)

__global__ __launch_bounds__(160, 3) void tail_mma_kernel(
    const __half* __restrict__ Q, const __half* __restrict__ Kp,
    const __half* __restrict__ hwT, float* __restrict__ out)
{
    extern __shared__ char ts[];
    const uint32_t sbase = smem_u32(ts);
    __half* codes = reinterpret_cast<__half*>(ts + T_CODE_OFF);
    float* snorm  = reinterpret_cast<float*>(ts + T_SN_OFF);

    const int tid  = threadIdx.x;
    const int lane = tid & 31;
    const int wid  = tid >> 5;
    const int b0   = (blockIdx.x >> 3) * 16;
    const int kvh  = blockIdx.x & 7;
    const float inv = 0.08838834764831845f;

    for (int c = tid; c < 2048; c += 160) {
        int row = c >> 4, seg = c & 15;
        int pl = seg >> 3;
        uint4 v = *reinterpret_cast<const uint4*>(
            hwT + (size_t)row * DD + pl * 64 + (seg & 7) * 8);
        uint32_t off = T_HW_OFF + pl * T_HW_PLANE +
                       sw128(row * 128 + (seg & 7) * 16);
        *reinterpret_cast<uint4*>(ts + off) = v;
    }

    {
        const int i = lane >> 1;
        const int h = lane & 1;
        const int b = b0 + i;
        const uint4* kptr = reinterpret_cast<const uint4*>(
            Kp + (size_t)b * KOUT + kvh * DD + h * 64);
        if (wid < 4) {
            const int head = kvh * 4 + wid;
            const uint4* qptr = reinterpret_cast<const uint4*>(
                Q + (size_t)b * HID + head * DD + h * 64);
            const int arow = wid * 16 + i;
            float dot = 0.f, qn2 = 0.f;
            #pragma unroll
            for (int c = 0; c < 8; c++) {
                uint4 qv = __ldg(qptr + c);
                uint4 kv = __ldg(kptr + c);
                const __half2* hq = reinterpret_cast<const __half2*>(&qv);
                const __half2* hk = reinterpret_cast<const __half2*>(&kv);
                #pragma unroll
                for (int j = 0; j < 4; j++) {
                    float2 fq = __half22float2(hq[j]);
                    float2 fk = __half22float2(hk[j]);
                    dot += fq.x * fk.x + fq.y * fk.y;
                    qn2 += fq.x * fq.x + fq.y * fq.y;
                }
                uint32_t off = T_A_OFF + h * T_A_PLANE +
                               sw128(arow * 128 + c * 16);
                *reinterpret_cast<uint4*>(ts + off) = qv;
            }
            dot += __shfl_xor_sync(0xffffffffu, dot, 1);
            qn2 += __shfl_xor_sync(0xffffffffu, qn2, 1);
            if (h == 0) {
                out[(size_t)b * HH + head] = dot * inv;
                snorm[arow] = qn2;
            }
        } else {
            const int arow = 64 + i;
            float kn2 = 0.f;
            #pragma unroll
            for (int c = 0; c < 8; c++) {
                uint4 kv = __ldg(kptr + c);
                const __half2* hk = reinterpret_cast<const __half2*>(&kv);
                #pragma unroll
                for (int j = 0; j < 4; j++) {
                    float2 fk = __half22float2(hk[j]);
                    kn2 += fk.x * fk.x + fk.y * fk.y;
                }
                uint32_t off = T_A_OFF + h * T_A_PLANE +
                               sw128(arow * 128 + c * 16);
                *reinterpret_cast<uint4*>(ts + off) = kv;
            }
            kn2 += __shfl_xor_sync(0xffffffffu, kn2, 1);
            if (h == 0) snorm[arow] = kn2;
        }
    }
    __syncthreads();

    {
        const int bi = lane >> 3;
        const int rr = lane & 7;
        const uint32_t a_row = wid * 16 + (bi & 1) * 8 + rr;
        const uint32_t a_col = (bi >> 1) * 16;
        const uint32_t b_rowb = (bi >> 1) * 8 + rr;
        const uint32_t b_col = (bi & 1) * 16;

        float acc[16][4];
        #pragma unroll
        for (int n = 0; n < 16; n++)
            #pragma unroll
            for (int e = 0; e < 4; e++) acc[n][e] = 0.f;

        #pragma unroll
        for (int kp = 0; kp < 8; kp++) {
            const int pl = kp >> 2;
            const int kb = (kp & 3) * 32;
            uint32_t afr[4];
            LDSM4(afr, sbase + T_A_OFF + pl * T_A_PLANE +
                       sw128(a_row * 128 + kb + a_col));
            #pragma unroll
            for (int nt = 0; nt < 8; nt++) {
                uint32_t r4[4];
                LDSM4(r4, sbase + T_HW_OFF + pl * T_HW_PLANE +
                          sw128((nt * 16 + b_rowb) * 128 + kb + b_col));
                uint32_t bf0[2] = {r4[0], r4[1]};
                uint32_t bf1[2] = {r4[2], r4[3]};
                mma16816(acc[nt * 2], afr, bf0);
                mma16816(acc[nt * 2 + 1], afr, bf1);
            }
        }

        const int gr  = lane >> 2;
        const int gc2 = (lane & 3) * 2;
        #pragma unroll
        for (int n = 0; n < 16; n++) {
            const int col = n * 8 + gc2;
            const int row0 = wid * 16 + gr;
            __half2 lo = __halves2half2(
                __float2half(0.5f * (tanh_fast(acc[n][0]) + 1.0f)),
                __float2half(0.5f * (tanh_fast(acc[n][1]) + 1.0f)));
            __half2 hi = __halves2half2(
                __float2half(0.5f * (tanh_fast(acc[n][2]) + 1.0f)),
                __float2half(0.5f * (tanh_fast(acc[n][3]) + 1.0f)));
            *reinterpret_cast<__half2*>(&codes[row0 * T_CODE_STR + col]) = lo;
            *reinterpret_cast<__half2*>(&codes[(row0 + 8) * T_CODE_STR + col]) = hi;
        }
    }
    __syncthreads();

    if (tid < 128) {
        const int qrow = tid >> 1;
        const int h = tid & 1;
        const int krow = 64 + (qrow & 15);
        const __half* qc = &codes[qrow * T_CODE_STR + h * 64];
        const __half* kc = &codes[krow * T_CODE_STR + h * 64];
        float s = 0.f;
        #pragma unroll
        for (int j = 0; j < 16; j++) {
            uint2 qv = *reinterpret_cast<const uint2*>(qc + j * 4);
            uint2 kv = *reinterpret_cast<const uint2*>(kc + j * 4);
            __half2 q0 = *reinterpret_cast<__half2*>(&qv.x);
            __half2 q1 = *reinterpret_cast<__half2*>(&qv.y);
            __half2 k0 = *reinterpret_cast<__half2*>(&kv.x);
            __half2 k1 = *reinterpret_cast<__half2*>(&kv.y);
            float2 a0 = __half22float2(q0), b0f = __half22float2(k0);
            float2 a1 = __half22float2(q1), b1f = __half22float2(k1);
            s += fabsf(a0.x - b0f.x) + fabsf(a0.y - b0f.y) +
                 fabsf(a1.x - b1f.x) + fabsf(a1.y - b1f.y);
        }
        s += __shfl_xor_sync(0xffffffffu, s, 1);
        if (h == 0) {
            const int i = qrow & 15;
            const int g = qrow >> 4;
            const int b = b0 + i;
            const float qn = sqrtf(snorm[qrow]);
            const float kn = sqrtf(snorm[64 + i]);
            out[(size_t)BB * HH + (size_t)b * HH + kvh * 4 + g] =
                (1.0f - 2.0f * s / (float)RBIT) * qn * kn * inv;
        }
    }
}

// ---------------------------------------------------------------------------
// Stream/event resources: created once on first (uncaptured) call.
// ---------------------------------------------------------------------------
struct SideStream {
    cudaStream_t s2, s3;
    cudaEvent_t evFork, evK, evWq;
    SideStream() {
        cudaStreamCreateWithFlags(&s2, cudaStreamNonBlocking);
        cudaStreamCreateWithFlags(&s3, cudaStreamNonBlocking);
        cudaEventCreateWithFlags(&evFork, cudaEventDisableTiming);
        cudaEventCreateWithFlags(&evK, cudaEventDisableTiming);
        cudaEventCreateWithFlags(&evWq, cudaEventDisableTiming);
    }
};
static SideStream& side() { static SideStream s; return s; }

// ---------------------------------------------------------------------------
extern "C" void kernel_launch(void* const* d_in, const int* in_sizes, int n_in,
                              void* d_out, int out_size)
{
    const float* q_hidden = (const float*)d_in[0];
    const float* k_hidden = (const float*)d_in[1];
    const float* q_w      = (const float*)d_in[2];
    const float* q_b      = (const float*)d_in[3];
    const float* k_w      = (const float*)d_in[4];
    const float* k_b      = (const float*)d_in[5];
    const float* hash_w   = (const float*)d_in[6];
    float* out = (float*)d_out;

    void *aq, *ak, *wq, *wk, *qp, *kp, *hwp;
    cudaGetSymbolAddress(&aq, g_Aq);
    cudaGetSymbolAddress(&ak, g_Ak);
    cudaGetSymbolAddress(&wq, g_Wq);
    cudaGetSymbolAddress(&wk, g_Wk);
    cudaGetSymbolAddress(&qp, g_Q);
    cudaGetSymbolAddress(&kp, g_K);
    cudaGetSymbolAddress(&hwp, g_hwT);

    cudaFuncSetAttribute(gemm_mma_kernel,
                         cudaFuncAttributeMaxDynamicSharedMemorySize, GEMM_SMEM);
    cudaFuncSetAttribute(tail_mma_kernel,
                         cudaFuncAttributeMaxDynamicSharedMemorySize, TAIL_SMEM);

    SideStream& ss = side();
    const size_t n4 = (size_t)BB * HID / 4;

    cudaEventRecord(ss.evFork, 0);

    // ---- s3: Wq transpose (parallel to convQ; gemmQ needs both) ----
    cudaStreamWaitEvent(ss.s3, ss.evFork, 0);
    split_w_kernel<<<dim3(HID / 32, HID / 32), 256, 0, ss.s3>>>(
        q_w, (__half*)wq, HID);
    cudaEventRecord(ss.evWq, ss.s3);

    // ---- s2: full K-side chain + hash_w prep ----
    cudaStreamWaitEvent(ss.s2, ss.evFork, 0);
    hw16_kernel<<<64, 256, 0, ss.s2>>>(hash_w, (__half*)hwp);
    split_w_kernel<<<dim3(KOUT / 32, HID / 32), 256, 0, ss.s2>>>(
        k_w, (__half*)wk, KOUT);
    tofp16_kernel<<<(unsigned)(n4 / 256), 256, 0, ss.s2>>>(
        (const float4*)k_hidden, (uint2*)ak, n4);
    gemm_mma_kernel<<<dim3(KOUT / BN, BB / BM), 256, GEMM_SMEM, ss.s2>>>(
        (const __half*)ak, (const __half*)wk, k_b, (__half*)kp, KOUT);
    cudaEventRecord(ss.evK, ss.s2);

    // ---- stream 0: Q-side chain ----
    tofp16_kernel<<<(unsigned)(n4 / 256), 256>>>(
        (const float4*)q_hidden, (uint2*)aq, n4);
    cudaStreamWaitEvent(0, ss.evWq, 0);
    gemm_mma_kernel<<<dim3(HID / BN, BB / BM), 256, GEMM_SMEM>>>(
        (const __half*)aq, (const __half*)wq, q_b, (__half*)qp, HID);

    // ---- join + tail ----
    cudaStreamWaitEvent(0, ss.evK, 0);
    tail_mma_kernel<<<(BB / 16) * KVH, 160, TAIL_SMEM>>>(
        (const __half*)qp, (const __half*)kp, (const __half*)hwp, out);
}